// round 16
// baseline (speedup 1.0000x reference)
#include <cuda_runtime.h>
#include <cuda_fp16.h>
#include <math.h>
#include <stdint.h>

#define BATCH 2
#define CIN 256
#define COUT 256
#define HHI 256
#define WHI 512
#define HLO 128
#define WLO 256
#define MMAX 129
#define LMAX 128
#define CPG 8
#define BC (BATCH*CIN)          /* 512    */
#define ROWS1 (BC*HHI)          /* 131072 */
#define ROWS2 (BC*HLO)          /* 65536  */
#define HWLO (HLO*WLO)          /* 32768  */

// -------- scratch (static device globals; no allocation allowed) --------
__device__ __align__(16) __half d_Xr[MMAX*ROWS1];         // single fp16
__device__ __align__(16) __half d_Xi[MMAX*ROWS1];
__device__ __align__(16) __half d_At_hi[MMAX*HLO*HHI];    // [m][klo][kh] hi/lo
__device__ __align__(16) __half d_At_lo[MMAX*HLO*HHI];
__device__ __align__(16) __half d_Whi[COUT*CIN];
__device__ __align__(16) __half d_Wlo[COUT*CIN];
__device__ __align__(16) __half d_Gr[MMAX*ROWS2];         // fp16 carrier
__device__ __align__(16) __half d_Gi[MMAX*ROWS2];
__device__ __align__(16) __half d_Yc[BC*HWLO];            // [b][c][hw], single fp16
__device__ __align__(16) __half d_Hh[BC*HWLO];            // [b][o][hw], fp16 carrier
__device__ float d_cps[1024*16], d_cps2[1024*16];
__device__ float d_mean[BATCH*32];
__device__ float d_rstd[BATCH*32];
// twiddle tables (filled once per launch by k_wsplit block 0)
__device__ float2 g_tw256[256];
__device__ float2 g_u512[129];
__device__ float2 g_tw128[128];
__device__ float2 g_w256[128];

// ======================= helpers =======================
__device__ __forceinline__ uint32_t smem_u32(const void* p) {
    uint32_t a;
    asm("{ .reg .u64 t; cvta.to.shared.u64 t, %1; cvt.u32.u64 %0, t; }" : "=r"(a) : "l"(p));
    return a;
}
__device__ __forceinline__ void ldsm_x4(uint32_t& r0, uint32_t& r1, uint32_t& r2, uint32_t& r3, uint32_t addr) {
    asm volatile("ldmatrix.sync.aligned.m8n8.x4.shared.b16 {%0,%1,%2,%3}, [%4];"
        : "=r"(r0), "=r"(r1), "=r"(r2), "=r"(r3) : "r"(addr));
}
__device__ __forceinline__ void ldsm_x4_t(uint32_t& r0, uint32_t& r1, uint32_t& r2, uint32_t& r3, uint32_t addr) {
    asm volatile("ldmatrix.sync.aligned.m8n8.x4.trans.shared.b16 {%0,%1,%2,%3}, [%4];"
        : "=r"(r0), "=r"(r1), "=r"(r2), "=r"(r3) : "r"(addr));
}
__device__ __forceinline__ void mma16816(float* d, const uint32_t* a, uint32_t b0, uint32_t b1) {
    asm volatile("mma.sync.aligned.m16n8k16.row.col.f32.f16.f16.f32 "
        "{%0,%1,%2,%3}, {%4,%5,%6,%7}, {%8,%9}, {%0,%1,%2,%3};"
        : "+f"(d[0]), "+f"(d[1]), "+f"(d[2]), "+f"(d[3])
        : "r"(a[0]), "r"(a[1]), "r"(a[2]), "r"(a[3]), "r"(b0), "r"(b1));
}
__device__ __forceinline__ void cp16(uint32_t dst, const void* src) {
    asm volatile("cp.async.cg.shared.global [%0], [%1], 16;" :: "r"(dst), "l"(src));
}
#define CP_COMMIT() asm volatile("cp.async.commit_group;" ::: "memory")
__device__ __forceinline__ void split2h(float v, __half& h, __half& l) {
    h = __float2half(v);
    l = __float2half(v - __half2float(h));
}

// stage layout: 3 tiles x 8KB = 24KB; 3 stages = 72KB
#define STG (24576)
#define GEMM_SMEM (3*STG)
#define BA_SMEM   (131072)

// non-trans tile [128 rows][32 k], 64B rows, swizzle c^((row>>1)&3)
#define OFF_NT(row, c) ((uint32_t)((row)<<6) + (uint32_t)(((c) ^ (((row)>>1)&3)) << 4))
// trans tile [32 k][128 n], 256B rows, swizzle c^(k&7)
#define OFF_T(k, c16)  ((uint32_t)((k)<<8) + (uint32_t)(((c16) ^ ((k)&7)) << 4))

// smem FFT pad
#define SWF(i) ((i) + ((((i)>>5))<<2))

// ============================================================
// GEMM core, both operands k-major:
// D(fp16) = A[128][256](single) @ (Bhi+Blo)[128][256]^T
// ============================================================
__device__ __forceinline__ void gemm_nn(
    const __half* __restrict__ A,
    const __half* __restrict__ Bhi, const __half* __restrict__ Blo,
    __half* __restrict__ D, int ldD, uint32_t sm)
{
    int tid = threadIdx.x;
    int wid = tid >> 5, lane = tid & 31;
    int wm = wid >> 1, wn = wid & 1;

    float acc[2][8][4];
    #pragma unroll
    for (int i=0;i<2;i++) for (int j=0;j<8;j++) for (int q=0;q<4;q++) acc[i][j][q] = 0.f;

    auto load_chunk = [&](int kc) {
        uint32_t base = sm + (kc % 3)*STG;
        #pragma unroll
        for (int e = tid; e < 512; e += 256) {
            int row = e >> 2, c = e & 3;
            uint32_t off = OFF_NT(row, c);
            size_t g = (size_t)row*256 + kc*32 + c*8;
            cp16(base          + off, A   + g);
            cp16(base +  8192  + off, Bhi + g);
            cp16(base + 16384  + off, Blo + g);
        }
        CP_COMMIT();
    };

    load_chunk(0); load_chunk(1); load_chunk(2);

    #pragma unroll 1
    for (int kc = 0; kc < 8; kc++) {
        if (kc < 6)      asm volatile("cp.async.wait_group 2;" ::: "memory");
        else if (kc == 6) asm volatile("cp.async.wait_group 1;" ::: "memory");
        else             asm volatile("cp.async.wait_group 0;" ::: "memory");
        __syncthreads();

        uint32_t base = sm + (kc % 3)*STG;
        uint32_t sA = base, sBhi = base + 8192, sBlo = base + 16384;

        #pragma unroll
        for (int ks = 0; ks < 2; ks++) {
            int c = ks*2 + (lane >> 4);
            uint32_t a[2][4];
            #pragma unroll
            for (int mi = 0; mi < 2; mi++) {
                int row = wm*32 + mi*16 + (lane & 15);
                uint32_t off = OFF_NT(row, c);
                ldsm_x4(a[mi][0], a[mi][1], a[mi][2], a[mi][3], sA + off);
            }
            uint32_t b[4][4];
            #pragma unroll
            for (int nj = 0; nj < 4; nj++) {
                int row = wn*64 + nj*16 + (lane & 7) + ((lane >> 3) & 1)*8;
                uint32_t off = OFF_NT(row, c);
                ldsm_x4(b[nj][0], b[nj][1], b[nj][2], b[nj][3], sBhi + off);
            }
            #pragma unroll
            for (int mi = 0; mi < 2; mi++)
                #pragma unroll
                for (int nj = 0; nj < 4; nj++) {
                    mma16816(acc[mi][nj*2],   a[mi], b[nj][0], b[nj][2]);
                    mma16816(acc[mi][nj*2+1], a[mi], b[nj][1], b[nj][3]);
                }
            #pragma unroll
            for (int nj = 0; nj < 4; nj++) {
                int row = wn*64 + nj*16 + (lane & 7) + ((lane >> 3) & 1)*8;
                uint32_t off = OFF_NT(row, c);
                ldsm_x4(b[nj][0], b[nj][1], b[nj][2], b[nj][3], sBlo + off);
            }
            #pragma unroll
            for (int mi = 0; mi < 2; mi++)
                #pragma unroll
                for (int nj = 0; nj < 4; nj++) {
                    mma16816(acc[mi][nj*2],   a[mi], b[nj][0], b[nj][2]);
                    mma16816(acc[mi][nj*2+1], a[mi], b[nj][1], b[nj][3]);
                }
        }
        __syncthreads();
        if (kc + 3 < 8) load_chunk(kc + 3);
    }

    int g = lane >> 2, tg = lane & 3;
    #pragma unroll
    for (int mi = 0; mi < 2; mi++) {
        int r0 = wm*32 + mi*16 + g;
        #pragma unroll
        for (int nt = 0; nt < 8; nt++) {
            int col = wn*64 + nt*8 + tg*2;
            __half2 v0, v1;
            v0.x = __float2half(acc[mi][nt][0]); v0.y = __float2half(acc[mi][nt][1]);
            v1.x = __float2half(acc[mi][nt][2]); v1.y = __float2half(acc[mi][nt][3]);
            *(__half2*)&D[(size_t)r0*ldD + col]     = v0;
            *(__half2*)&D[(size_t)(r0+8)*ldD + col] = v1;
        }
    }
}

// ============================================================
// GEMM core, A k-major (hi+lo), B row-major [256 k][N] (single, trans).
// Fused GroupNorm partial stats (from fp32 accumulators). D stored fp16.
// ============================================================
__device__ __forceinline__ void gemm_kn(
    const __half* __restrict__ Ahi, const __half* __restrict__ Alo,
    const __half* __restrict__ Bh, size_t ldB,
    __half* __restrict__ D, int ldD, const float* __restrict__ bias, uint32_t sm,
    char* smc, float* cps, float* cps2, int blin)
{
    int tid = threadIdx.x;
    int wid = tid >> 5, lane = tid & 31;
    int wm = wid >> 1, wn = wid & 1;

    float acc[2][8][4];
    #pragma unroll
    for (int i=0;i<2;i++) for (int j=0;j<8;j++) for (int q=0;q<4;q++) acc[i][j][q] = 0.f;

    auto load_chunk = [&](int kc) {
        uint32_t base = sm + (kc % 3)*STG;
        #pragma unroll
        for (int e = tid; e < 512; e += 256) {
            int row = e >> 2, c = e & 3;
            uint32_t off = OFF_NT(row, c);
            size_t gA = (size_t)row*256 + kc*32 + c*8;
            cp16(base         + off, Ahi + gA);
            cp16(base +  8192 + off, Alo + gA);
            int kr = e >> 4, c16 = e & 15;
            uint32_t offb = OFF_T(kr, c16);
            size_t gB = (size_t)(kc*32 + kr)*ldB + c16*8;
            cp16(base + 16384 + offb, Bh + gB);
        }
        CP_COMMIT();
    };

    load_chunk(0); load_chunk(1); load_chunk(2);

    #pragma unroll 1
    for (int kc = 0; kc < 8; kc++) {
        if (kc < 6)      asm volatile("cp.async.wait_group 2;" ::: "memory");
        else if (kc == 6) asm volatile("cp.async.wait_group 1;" ::: "memory");
        else             asm volatile("cp.async.wait_group 0;" ::: "memory");
        __syncthreads();

        uint32_t base = sm + (kc % 3)*STG;
        uint32_t sAhi = base, sAlo = base + 8192, sBh = base + 16384;

        #pragma unroll
        for (int ks = 0; ks < 2; ks++) {
            int c = ks*2 + (lane >> 4);
            uint32_t a_h[2][4], a_l[2][4];
            #pragma unroll
            for (int mi = 0; mi < 2; mi++) {
                int row = wm*32 + mi*16 + (lane & 15);
                uint32_t off = OFF_NT(row, c);
                ldsm_x4(a_h[mi][0], a_h[mi][1], a_h[mi][2], a_h[mi][3], sAhi + off);
                ldsm_x4(a_l[mi][0], a_l[mi][1], a_l[mi][2], a_l[mi][3], sAlo + off);
            }
            int kr = ks*16 + (lane & 7) + ((lane >> 3) & 1)*8;
            uint32_t b[4][4];
            #pragma unroll
            for (int nj = 0; nj < 4; nj++) {
                int n = wn*64 + nj*16 + ((lane >> 4) & 1)*8;
                uint32_t off = OFF_T(kr, (n >> 3));
                ldsm_x4_t(b[nj][0], b[nj][1], b[nj][2], b[nj][3], sBh + off);
            }
            #pragma unroll
            for (int mi = 0; mi < 2; mi++)
                #pragma unroll
                for (int nj = 0; nj < 4; nj++) {
                    mma16816(acc[mi][nj*2],   a_h[mi], b[nj][0], b[nj][1]);
                    mma16816(acc[mi][nj*2+1], a_h[mi], b[nj][2], b[nj][3]);
                }
            #pragma unroll
            for (int mi = 0; mi < 2; mi++)
                #pragma unroll
                for (int nj = 0; nj < 4; nj++) {
                    mma16816(acc[mi][nj*2],   a_l[mi], b[nj][0], b[nj][1]);
                    mma16816(acc[mi][nj*2+1], a_l[mi], b[nj][2], b[nj][3]);
                }
        }
        __syncthreads();
        if (kc + 3 < 8) load_chunk(kc + 3);
    }

    int g = lane >> 2, tg = lane & 3;
    int slot = wn*4 + tg;
    float* srow  = (float*)smc;          // [128][8]
    float* srow2 = srow + 1024;          // [128][8]
    float* rtot  = srow + 2048;          // [128]
    float* rtot2 = srow + 2176;          // [128]
    #pragma unroll
    for (int mi = 0; mi < 2; mi++) {
        int r0 = wm*32 + mi*16 + g;
        float bv0 = bias[r0], bv1 = bias[r0+8];
        float s0=0.f, q0=0.f, s1=0.f, q1=0.f;
        #pragma unroll
        for (int nt = 0; nt < 8; nt++) {
            int col = wn*64 + nt*8 + tg*2;
            float v0 = acc[mi][nt][0] + bv0, v1 = acc[mi][nt][1] + bv0;
            float v2 = acc[mi][nt][2] + bv1, v3 = acc[mi][nt][3] + bv1;
            __half2 p0, p1;
            p0.x = __float2half(v0); p0.y = __float2half(v1);
            p1.x = __float2half(v2); p1.y = __float2half(v3);
            *(__half2*)&D[(size_t)r0*ldD + col]     = p0;
            *(__half2*)&D[(size_t)(r0+8)*ldD + col] = p1;
            s0 += v0 + v1; q0 += v0*v0 + v1*v1;
            s1 += v2 + v3; q1 += v2*v2 + v3*v3;
        }
        srow [r0*8 + slot] = s0;  srow2[r0*8 + slot] = q0;
        srow [(r0+8)*8 + slot] = s1;  srow2[(r0+8)*8 + slot] = q1;
    }
    __syncthreads();
    if (tid < 128) {
        float s=0.f, q=0.f;
        #pragma unroll
        for (int j = 0; j < 8; j++) { s += srow[tid*8+j]; q += srow2[tid*8+j]; }
        rtot[tid] = s; rtot2[tid] = q;
    }
    __syncthreads();
    if (tid < 16) {
        float s=0.f, q=0.f;
        #pragma unroll
        for (int j = 0; j < 8; j++) { s += rtot[tid*8+j]; q += rtot2[tid*8+j]; }
        cps [blin*16 + tid] = s;
        cps2[blin*16 + tid] = q;
    }
}

// ============================================================
// Stage 0: split conv weights + fill twiddle tables (block 0).
// ============================================================
__global__ void k_wsplit(const float* __restrict__ w) {
    int i = blockIdx.x*256 + threadIdx.x;   // 65536 total
    __half h, l;
    split2h(w[i], h, l);
    d_Whi[i] = h; d_Wlo[i] = l;
    if (blockIdx.x == 0) {
        int t = threadIdx.x;
        if (t < 256) { float s,c; sincosf(6.283185307179586f*(float)t/256.0f,&s,&c); g_tw256[t]=make_float2(c,-s); }
        if (t < 129) { float s,c; sincosf(-6.283185307179586f*(float)t/512.0f,&s,&c); g_u512[t]=make_float2(c,s); }
        if (t < 128) { float s,c; sincosf(6.283185307179586f*(float)t/128.0f,&s,&c); g_tw128[t]=make_float2(c,s); }
        if (t < 128) { float s,c; sincosf(6.283185307179586f*(float)t/256.0f,&s,&c); g_w256[t]=make_float2(c,s); }
    }
}

// ============================================================
// Stage 1: rfft(512) per row via packed radix-4 256-pt FFT. Output single fp16.
// ============================================================
__global__ void __launch_bounds__(512) k_fft_fwd(const float* __restrict__ x) {
    __shared__ float sre[16*288];
    __shared__ float sim[16*288];
    __shared__ float2 tw[256];
    __shared__ float2 ue[129];
    int tid = threadIdx.x;
    if (tid < 256) tw[tid] = g_tw256[tid];
    if (tid < 129) ue[tid] = g_u512[tid];
    __syncthreads();
    int w = tid >> 5, lane = tid & 31;
    float* re = sre + w*288;
    float* im = sim + w*288;
    int row = blockIdx.x*16 + w;
    const float4* xr4 = (const float4*)(x + (size_t)row*512);
    #pragma unroll
    for (int j = 0; j < 4; j++) {
        float4 v = xr4[lane + 32*j];
        int f  = lane + 32*j;
        int r0 = __brev(2*f)   >> 24;
        int r1 = __brev(2*f+1) >> 24;
        re[SWF(r0)]=v.x; im[SWF(r0)]=v.y;
        re[SWF(r1)]=v.z; im[SWF(r1)]=v.w;
    }
    __syncwarp();
    #pragma unroll
    for (int h = 0; h < 2; h++) {
        int p = 4*(lane + 32*h);
        int a = SWF(p);
        float4 vr = *(float4*)&re[a];
        float4 vi = *(float4*)&im[a];
        float t0r=vr.x,t0i=vi.x, t1r=vr.z,t1i=vi.z, t2r=vr.y,t2i=vi.y, t3r=vr.w,t3i=vi.w;
        float s0r=t0r+t2r, s0i=t0i+t2i, d0r=t0r-t2r, d0i=t0i-t2i;
        float s1r=t1r+t3r, s1i=t1i+t3i, d1r=t1r-t3r, d1i=t1i-t3i;
        float4 yr, yi;
        yr.x = s0r+s1r; yi.x = s0i+s1i;
        yr.y = d0r+d1i; yi.y = d0i-d1r;
        yr.z = s0r-s1r; yi.z = s0i-s1i;
        yr.w = d0r-d1i; yi.w = d0i+d1r;
        *(float4*)&re[a] = yr; *(float4*)&im[a] = yi;
    }
    __syncwarp();
    #pragma unroll
    for (int rq = 0; rq < 3; rq++) {
        int Q = 4 << (2*rq);
        int step = 16 >> (2*rq);
        #pragma unroll
        for (int h = 0; h < 2; h++) {
            int b = lane + 32*h;
            int j = b & (Q-1);
            int p = ((b & ~(Q-1)) << 2) + j;
            float2 w1 = tw[(j*step) & 255];
            float2 w2 = tw[(2*j*step) & 255];
            float2 w3 = tw[(3*j*step) & 255];
            int a0 = SWF(p), a1 = SWF(p+2*Q), a2 = SWF(p+Q), a3 = SWF(p+3*Q);
            float x0r=re[a0], x0i=im[a0];
            float x1r=re[a1], x1i=im[a1];
            float x2r=re[a2], x2i=im[a2];
            float x3r=re[a3], x3i=im[a3];
            float t1r = x1r*w1.x - x1i*w1.y, t1i = x1r*w1.y + x1i*w1.x;
            float t2r = x2r*w2.x - x2i*w2.y, t2i = x2r*w2.y + x2i*w2.x;
            float t3r = x3r*w3.x - x3i*w3.y, t3i = x3r*w3.y + x3i*w3.x;
            float s0r=x0r+t2r, s0i=x0i+t2i, d0r=x0r-t2r, d0i=x0i-t2i;
            float s1r=t1r+t3r, s1i=t1i+t3i, d1r=t1r-t3r, d1i=t1i-t3i;
            re[a0]=s0r+s1r; im[a0]=s0i+s1i;
            re[a2]=d0r+d1i; im[a2]=d0i-d1r;
            re[a1]=s0r-s1r; im[a1]=s0i-s1i;
            re[a3]=d0r-d1i; im[a3]=d0i+d1r;
        }
        __syncwarp();
    }
    const float SC = 0.012271846303085129f;  // 2*pi/512
    float ro[5], io[5];
    #pragma unroll
    for (int j = 0; j < 5; j++) {
        int k = lane + 32*j;
        if (k <= 128) {
            int km = (256-k) & 255;
            float zr=re[SWF(k)],  zi= im[SWF(k)];
            float mr=re[SWF(km)], mi=-im[SWF(km)];
            float er=0.5f*(zr+mr), ei=0.5f*(zi+mi);
            float dr=0.5f*(zr-mr), di=0.5f*(zi-mi);
            float pr=di, pi=-dr;
            float wr=ue[k].x, wi=ue[k].y;
            float qr=pr*wr-pi*wi, qi=pr*wi+pi*wr;
            ro[j] = (er+qr)*SC;
            io[j] = (ei+qi)*SC;
        }
    }
    __syncthreads();
    float* ore = sre;   // reuse: [129][16]
    float* oim = sim;
    #pragma unroll
    for (int j = 0; j < 5; j++) {
        int k = lane + 32*j;
        if (k <= 128) { ore[k*16+w] = ro[j]; oim[k*16+w] = io[j]; }
    }
    __syncthreads();
    int base = blockIdx.x*16;
    for (int idx = tid; idx < 129*8; idx += 512) {
        int m = idx >> 3, rr = (idx & 7) << 1;
        size_t o = (size_t)m*ROWS1 + base + rr;
        __half2 v;
        v.x = __float2half(ore[m*16+rr]);
        v.y = __float2half(ore[m*16+rr+1]);
        *(__half2*)&d_Xr[o] = v;
        v.x = __float2half(oim[m*16+rr]);
        v.y = __float2half(oim[m*16+rr+1]);
        *(__half2*)&d_Xi[o] = v;
    }
}

// ============================================================
// Stage 2c: At[m][klo][kh] = sum_l P[l][klo] W[l][kh] via fp16 3-term mma.
// ============================================================
__global__ void __launch_bounds__(256) k_buildA_mma(const float* __restrict__ wmat,
                                                    const float* __restrict__ pct) {
    extern __shared__ __align__(128) char dsm[];
    uint32_t sm = smem_u32(dsm);
    int tid = threadIdx.x;
    int wid = tid >> 5, lane = tid & 31;
    int wm = wid >> 1, wn = wid & 1;
    int m = blockIdx.y, kh0 = blockIdx.x * 128;

    const float* Pg = pct  + (size_t)m*LMAX*HLO;
    const float* Wg = wmat + (size_t)m*LMAX*HHI + kh0;

    #pragma unroll
    for (int p = 0; p < 8; p++) {
        int gi = p*256 + tid;
        int l = gi >> 4, c16 = gi & 15;
        uint32_t off = (uint32_t)((l >> 5) << 13) + OFF_T(l & 31, c16);
        {
            const float* sp = Pg + (size_t)l*HLO + c16*8;
            float4 v0 = *(const float4*)sp;
            float4 v1 = *(const float4*)(sp+4);
            __half h[8], lo[8];
            split2h(v0.x,h[0],lo[0]); split2h(v0.y,h[1],lo[1]); split2h(v0.z,h[2],lo[2]); split2h(v0.w,h[3],lo[3]);
            split2h(v1.x,h[4],lo[4]); split2h(v1.y,h[5],lo[5]); split2h(v1.z,h[6],lo[6]); split2h(v1.w,h[7],lo[7]);
            *(uint4*)(dsm + off)          = *(uint4*)h;
            *(uint4*)(dsm + 32768 + off)  = *(uint4*)lo;
        }
        {
            const float* sw = Wg + (size_t)l*HHI + c16*8;
            float4 v0 = *(const float4*)sw;
            float4 v1 = *(const float4*)(sw+4);
            __half h[8], lo[8];
            split2h(v0.x,h[0],lo[0]); split2h(v0.y,h[1],lo[1]); split2h(v0.z,h[2],lo[2]); split2h(v0.w,h[3],lo[3]);
            split2h(v1.x,h[4],lo[4]); split2h(v1.y,h[5],lo[5]); split2h(v1.z,h[6],lo[6]); split2h(v1.w,h[7],lo[7]);
            *(uint4*)(dsm + 65536 + off)  = *(uint4*)h;
            *(uint4*)(dsm + 98304 + off)  = *(uint4*)lo;
        }
    }
    __syncthreads();

    float acc[2][8][4];
    #pragma unroll
    for (int i=0;i<2;i++) for (int j=0;j<8;j++) for (int q=0;q<4;q++) acc[i][j][q] = 0.f;

    #pragma unroll 1
    for (int kc = 0; kc < 4; kc++) {
        uint32_t cb = (uint32_t)(kc << 13);
        uint32_t sPh = sm + cb, sPl = sm + 32768 + cb, sWh = sm + 65536 + cb, sWl = sm + 98304 + cb;

        #pragma unroll
        for (int ks = 0; ks < 2; ks++) {
            int kr = ks*16 + (lane & 7) + ((lane >> 3) & 1)*8;
            uint32_t a_h[2][4], a_l[2][4];
            #pragma unroll
            for (int mi = 0; mi < 2; mi++) {
                int mcol = wm*4 + mi*2 + ((lane >> 4) & 1);
                uint32_t off = OFF_T(kr, mcol);
                uint32_t r0,r1,r2,r3;
                ldsm_x4_t(r0, r1, r2, r3, sPh + off);
                a_h[mi][0]=r0; a_h[mi][1]=r2; a_h[mi][2]=r1; a_h[mi][3]=r3;
                ldsm_x4_t(r0, r1, r2, r3, sPl + off);
                a_l[mi][0]=r0; a_l[mi][1]=r2; a_l[mi][2]=r1; a_l[mi][3]=r3;
            }
            uint32_t b[4][4];
            #pragma unroll
            for (int nj = 0; nj < 4; nj++) {
                int n = wn*64 + nj*16 + ((lane >> 4) & 1)*8;
                uint32_t off = OFF_T(kr, (n >> 3));
                ldsm_x4_t(b[nj][0], b[nj][1], b[nj][2], b[nj][3], sWh + off);
            }
            #pragma unroll
            for (int mi = 0; mi < 2; mi++)
                #pragma unroll
                for (int nj = 0; nj < 4; nj++) {
                    mma16816(acc[mi][nj*2],   a_h[mi], b[nj][0], b[nj][1]);
                    mma16816(acc[mi][nj*2+1], a_h[mi], b[nj][2], b[nj][3]);
                }
            #pragma unroll
            for (int mi = 0; mi < 2; mi++)
                #pragma unroll
                for (int nj = 0; nj < 4; nj++) {
                    mma16816(acc[mi][nj*2],   a_l[mi], b[nj][0], b[nj][1]);
                    mma16816(acc[mi][nj*2+1], a_l[mi], b[nj][2], b[nj][3]);
                }
            #pragma unroll
            for (int nj = 0; nj < 4; nj++) {
                int n = wn*64 + nj*16 + ((lane >> 4) & 1)*8;
                uint32_t off = OFF_T(kr, (n >> 3));
                ldsm_x4_t(b[nj][0], b[nj][1], b[nj][2], b[nj][3], sWl + off);
            }
            #pragma unroll
            for (int mi = 0; mi < 2; mi++)
                #pragma unroll
                for (int nj = 0; nj < 4; nj++) {
                    mma16816(acc[mi][nj*2],   a_h[mi], b[nj][0], b[nj][1]);
                    mma16816(acc[mi][nj*2+1], a_h[mi], b[nj][2], b[nj][3]);
                }
        }
    }

    int g = lane >> 2, tg = lane & 3;
    size_t Abase = (size_t)m*(HLO*HHI);
    #pragma unroll
    for (int mi = 0; mi < 2; mi++) {
        #pragma unroll
        for (int half = 0; half < 2; half++) {
            int r = wm*32 + mi*16 + g + half*8;
            #pragma unroll
            for (int nt = 0; nt < 8; nt++) {
                int col = kh0 + wn*64 + nt*8 + tg*2;
                __half h0,l0,h1,l1;
                split2h(acc[mi][nt][half*2],   h0, l0);
                split2h(acc[mi][nt][half*2+1], h1, l1);
                __half2 vh; vh.x=h0; vh.y=h1;
                __half2 vl; vl.x=l0; vl.y=l1;
                *(__half2*)&d_At_hi[Abase + (size_t)r*HHI + col] = vh;
                *(__half2*)&d_At_lo[Abase + (size_t)r*HHI + col] = vl;
            }
        }
    }
}

// ============================================================
// Stage 3: Legendre per-m GEMM (X single, At hi/lo). G fp16.
// Forced 3 CTAs/SM (register cap ~85).
// ============================================================
__global__ void __launch_bounds__(256, 3) k_legendre_mma() {
    extern __shared__ __align__(128) char dsm[];
    int m = blockIdx.y;
    int bx = blockIdx.x;
    int half = bx >> 2;
    int bc0  = (bx & 3) * 128;
    size_t xo = (size_t)m*ROWS1 + (size_t)bc0*HHI;
    const __half* A;
    __half* D;
    if (half) { A = d_Xi + xo; D = d_Gi; }
    else      { A = d_Xr + xo; D = d_Gr; }
    D += (size_t)m*ROWS2 + (size_t)bc0*HLO;
    const __half* Bh = d_At_hi + (size_t)m*(HLO*HHI);
    const __half* Bl = d_At_lo + (size_t)m*(HLO*HHI);
    gemm_nn(A, Bh, Bl, D, HLO, smem_u32(dsm));
}

// ============================================================
// Stage 4: irfft(n=256)*256 per row. G fp16 in, single fp16 out.
// ============================================================
__global__ void __launch_bounds__(512) k_ifft() {
    __shared__ float gre[129*16], gim[129*16];
    __shared__ float sre[16*144], sim[16*144];
    __shared__ float2 tw2[128];
    __shared__ float2 wq[128];
    int tid = threadIdx.x;
    if (tid < 128) tw2[tid] = g_tw128[tid];
    if (tid >= 128 && tid < 256) wq[tid-128] = g_w256[tid-128];
    int base = blockIdx.x*16;
    for (int idx = tid; idx < 129*16; idx += 512) {
        int m = idx >> 4, r = idx & 15;
        gre[idx] = __half2float(d_Gr[m*ROWS2 + base + r]);
        gim[idx] = __half2float(d_Gi[m*ROWS2 + base + r]);
    }
    __syncthreads();
    int w = tid >> 5, lane = tid & 31;
    float* re = sre + w*144;
    float* im = sim + w*144;
    #pragma unroll 4
    for (int k = lane; k < 128; k += 32) {
        float ar = gre[k*16+w],        ai =  gim[k*16+w];
        float br = gre[(128-k)*16+w],  bi = -gim[(128-k)*16+w];
        float wr = wq[k].x, wi = wq[k].y;
        float c1r = 1.f - wi, c1i =  wr;
        float c2r = 1.f + wi, c2i = -wr;
        float Zr = ar*c1r - ai*c1i + br*c2r - bi*c2i;
        float Zi = ar*c1i + ai*c1r + br*c2i + bi*c2r;
        int rv = __brev(k) >> 25;
        re[SWF(rv)] = Zr; im[SWF(rv)] = Zi;
    }
    __syncwarp();
    {
        int p = 4*lane;
        int a = SWF(p);
        float4 vr = *(float4*)&re[a];
        float4 vi = *(float4*)&im[a];
        float t0r=vr.x,t0i=vi.x, t1r=vr.z,t1i=vi.z, t2r=vr.y,t2i=vi.y, t3r=vr.w,t3i=vi.w;
        float s0r=t0r+t2r, s0i=t0i+t2i, d0r=t0r-t2r, d0i=t0i-t2i;
        float s1r=t1r+t3r, s1i=t1i+t3i, d1r=t1r-t3r, d1i=t1i-t3i;
        float4 yr, yi;
        yr.x = s0r+s1r; yi.x = s0i+s1i;
        yr.y = d0r-d1i; yi.y = d0i+d1r;
        yr.z = s0r-s1r; yi.z = s0i-s1i;
        yr.w = d0r+d1i; yi.w = d0i-d1r;
        *(float4*)&re[a] = yr; *(float4*)&im[a] = yi;
    }
    __syncwarp();
    #pragma unroll
    for (int rq = 0; rq < 2; rq++) {
        int Q = 4 << (2*rq);
        int step = 8 >> (2*rq);
        int b = lane;
        int j = b & (Q-1);
        int p = ((b & ~(Q-1)) << 2) + j;
        float2 w1 = tw2[(j*step) & 127];
        float2 w2 = tw2[(2*j*step) & 127];
        float2 w3 = tw2[(3*j*step) & 127];
        int a0 = SWF(p), a1 = SWF(p+2*Q), a2 = SWF(p+Q), a3 = SWF(p+3*Q);
        float x0r=re[a0], x0i=im[a0];
        float x1r=re[a1], x1i=im[a1];
        float x2r=re[a2], x2i=im[a2];
        float x3r=re[a3], x3i=im[a3];
        float t1r = x1r*w1.x - x1i*w1.y, t1i = x1r*w1.y + x1i*w1.x;
        float t2r = x2r*w2.x - x2i*w2.y, t2i = x2r*w2.y + x2i*w2.x;
        float t3r = x3r*w3.x - x3i*w3.y, t3i = x3r*w3.y + x3i*w3.x;
        float s0r=x0r+t2r, s0i=x0i+t2i, d0r=x0r-t2r, d0i=x0i-t2i;
        float s1r=t1r+t3r, s1i=t1i+t3i, d1r=t1r-t3r, d1i=t1i-t3i;
        re[a0]=s0r+s1r; im[a0]=s0i+s1i;
        re[a2]=d0r-d1i; im[a2]=d0i+d1r;
        re[a1]=s0r-s1r; im[a1]=s0i-s1i;
        re[a3]=d0r+d1i; im[a3]=d0i-d1r;
        __syncwarp();
    }
    #pragma unroll
    for (int h = 0; h < 2; h++) {
        int p = lane + 32*h;
        float2 wv = tw2[p];
        int a0 = SWF(p), a1 = SWF(p+64);
        float x0r=re[a0], x0i=im[a0];
        float x1r=re[a1], x1i=im[a1];
        float tr = x1r*wv.x - x1i*wv.y, ti = x1r*wv.y + x1i*wv.x;
        re[a0]=x0r+tr; im[a0]=x0i+ti;
        re[a1]=x0r-tr; im[a1]=x0i-ti;
    }
    __syncwarp();
    __half2* yh = (__half2*)d_Yc + (size_t)(base + w)*128;
    #pragma unroll 4
    for (int n = lane; n < 128; n += 32) {
        __half2 v;
        v.x = __float2half(re[SWF(n)]);
        v.y = __float2half(im[SWF(n)]);
        yh[n] = v;
    }
}

// ============================================================
// Stage 5: 1x1 conv + fused GN partial stats. H stored fp16.
// Forced 3 CTAs/SM (register cap ~85).
// ============================================================
__global__ void __launch_bounds__(256, 3) k_conv_mma(const float* __restrict__ bias) {
    extern __shared__ __align__(128) char dsm[];
    int b = blockIdx.z, o0 = blockIdx.y*128, hw0 = blockIdx.x*128;
    int blin = (b*2 + blockIdx.y)*256 + blockIdx.x;
    const __half* Ah = d_Whi + (size_t)o0*CIN;
    const __half* Al = d_Wlo + (size_t)o0*CIN;
    const __half* Bh = d_Yc + (size_t)b*CIN*HWLO + hw0;
    __half* D = d_Hh + ((size_t)b*COUT + o0)*HWLO + hw0;
    gemm_kn(Ah, Al, Bh, (size_t)HWLO, D, HWLO, bias + o0, smem_u32(dsm),
            dsm, d_cps, d_cps2, blin);
}

// ============================================================
// Stage 6: GroupNorm final stats — 64 blocks, parallel tree.
// ============================================================
__global__ void k_gnfin() {
    __shared__ double sh[256], sh2[256];
    int bg = blockIdx.x;
    int b = bg >> 5, g = bg & 31;
    int y = g >> 4, gi = g & 15;
    int t = threadIdx.x;
    int idx = ((b*2 + y)*256 + t)*16 + gi;
    sh[t]  = (double)d_cps [idx];
    sh2[t] = (double)d_cps2[idx];
    __syncthreads();
    for (int st = 128; st > 0; st >>= 1) {
        if (t < st) { sh[t] += sh[t+st]; sh2[t] += sh2[t+st]; }
        __syncthreads();
    }
    if (t == 0) {
        const double N = (double)(CPG*HWLO);
        double mean = sh[0] / N;
        double var  = sh2[0] / N - mean*mean;
        d_mean[bg] = (float)mean;
        d_rstd[bg] = rsqrtf((float)var + 1e-5f);
    }
}

// ============================================================
// Stage 7: normalize + affine + exact GELU (8 halves/thread)
// ============================================================
__global__ void k_gnapply(const float* __restrict__ gamma, const float* __restrict__ beta,
                          float* __restrict__ out) {
    int base = blockIdx.x*256 + threadIdx.x;   // uint4 index: 8 halves
    uint4 hv = ((const uint4*)d_Hh)[base];
    int e0 = base * 8;
    int o  = (e0 >> 15) & 255;
    int bg = e0 >> 18;
    float a  = gamma[o] * d_rstd[bg];
    float b2 = beta[o] - d_mean[bg] * a;
    __half2* hp = (__half2*)&hv;
    float4 r0, r1;
    float v[8];
    #pragma unroll
    for (int j = 0; j < 4; j++) {
        float2 f = __half22float2(hp[j]);
        v[2*j]   = f.x*a + b2;
        v[2*j+1] = f.y*a + b2;
    }
    r0.x = v[0]*normcdff(v[0]); r0.y = v[1]*normcdff(v[1]);
    r0.z = v[2]*normcdff(v[2]); r0.w = v[3]*normcdff(v[3]);
    r1.x = v[4]*normcdff(v[4]); r1.y = v[5]*normcdff(v[5]);
    r1.z = v[6]*normcdff(v[6]); r1.w = v[7]*normcdff(v[7]);
    ((float4*)out)[base*2]     = r0;
    ((float4*)out)[base*2 + 1] = r1;
}

// ============================================================
extern "C" void kernel_launch(void* const* d_in, const int* in_sizes, int n_in,
                              void* d_out, int out_size) {
    const float* x      = (const float*)d_in[0];
    const float* conv_w = (const float*)d_in[1];
    const float* conv_b = (const float*)d_in[2];
    const float* gamma  = (const float*)d_in[3];
    const float* beta   = (const float*)d_in[4];
    const float* wmat   = (const float*)d_in[5];
    const float* pct    = (const float*)d_in[6];
    float* out = (float*)d_out;

    cudaFuncSetAttribute(k_buildA_mma,   cudaFuncAttributeMaxDynamicSharedMemorySize, BA_SMEM);
    cudaFuncSetAttribute(k_legendre_mma, cudaFuncAttributeMaxDynamicSharedMemorySize, GEMM_SMEM);
    cudaFuncSetAttribute(k_conv_mma,     cudaFuncAttributeMaxDynamicSharedMemorySize, GEMM_SMEM);

    k_wsplit      <<<256, 256>>>(conv_w);
    k_fft_fwd     <<<ROWS1/16, 512>>>(x);
    k_buildA_mma  <<<dim3(2, MMAX), 256, BA_SMEM>>>(wmat, pct);
    k_legendre_mma<<<dim3(8, MMAX), 256, GEMM_SMEM>>>();
    k_ifft        <<<ROWS2/16, 512>>>();
    k_conv_mma    <<<dim3(HWLO/128, COUT/128, BATCH), 256, GEMM_SMEM>>>(conv_b);
    k_gnfin       <<<64, 256>>>();
    k_gnapply     <<<(BC*HWLO)/8/256, 256>>>(gamma, beta, out);
}

// round 17
// speedup vs baseline: 1.1238x; 1.1238x over previous
#include <cuda_runtime.h>
#include <cuda_fp16.h>
#include <math.h>
#include <stdint.h>

#define BATCH 2
#define CIN 256
#define COUT 256
#define HHI 256
#define WHI 512
#define HLO 128
#define WLO 256
#define MMAX 129
#define LMAX 128
#define CPG 8
#define BC (BATCH*CIN)          /* 512    */
#define ROWS1 (BC*HHI)          /* 131072 */
#define ROWS2 (BC*HLO)          /* 65536  */
#define HWLO (HLO*WLO)          /* 32768  */

// -------- scratch (static device globals; no allocation allowed) --------
__device__ __align__(16) __half d_Xr[MMAX*ROWS1];         // single fp16
__device__ __align__(16) __half d_Xi[MMAX*ROWS1];
__device__ __align__(16) __half d_At_hi[MMAX*HLO*HHI];    // [m][klo][kh] hi/lo
__device__ __align__(16) __half d_At_lo[MMAX*HLO*HHI];
__device__ __align__(16) __half d_Whi[COUT*CIN];
__device__ __align__(16) __half d_Wlo[COUT*CIN];
__device__ __align__(16) __half d_Gr[MMAX*ROWS2];         // fp16 carrier
__device__ __align__(16) __half d_Gi[MMAX*ROWS2];
__device__ __align__(16) __half d_Yc[BC*HWLO];            // [b][c][hw], single fp16
__device__ __align__(16) __half d_Hh[BC*HWLO];            // [b][o][hw], fp16 carrier
__device__ float d_cps[1024*16], d_cps2[1024*16];
__device__ float d_mean[BATCH*32];
__device__ float d_rstd[BATCH*32];
// twiddle tables (filled once per launch by k_wsplit block 0)
__device__ float2 g_tw256[256];
__device__ float2 g_u512[129];
__device__ float2 g_tw128[128];
__device__ float2 g_w256[128];

// ======================= helpers =======================
__device__ __forceinline__ uint32_t smem_u32(const void* p) {
    uint32_t a;
    asm("{ .reg .u64 t; cvta.to.shared.u64 t, %1; cvt.u32.u64 %0, t; }" : "=r"(a) : "l"(p));
    return a;
}
__device__ __forceinline__ void ldsm_x4(uint32_t& r0, uint32_t& r1, uint32_t& r2, uint32_t& r3, uint32_t addr) {
    asm volatile("ldmatrix.sync.aligned.m8n8.x4.shared.b16 {%0,%1,%2,%3}, [%4];"
        : "=r"(r0), "=r"(r1), "=r"(r2), "=r"(r3) : "r"(addr));
}
__device__ __forceinline__ void ldsm_x4_t(uint32_t& r0, uint32_t& r1, uint32_t& r2, uint32_t& r3, uint32_t addr) {
    asm volatile("ldmatrix.sync.aligned.m8n8.x4.trans.shared.b16 {%0,%1,%2,%3}, [%4];"
        : "=r"(r0), "=r"(r1), "=r"(r2), "=r"(r3) : "r"(addr));
}
__device__ __forceinline__ void mma16816(float* d, const uint32_t* a, uint32_t b0, uint32_t b1) {
    asm volatile("mma.sync.aligned.m16n8k16.row.col.f32.f16.f16.f32 "
        "{%0,%1,%2,%3}, {%4,%5,%6,%7}, {%8,%9}, {%0,%1,%2,%3};"
        : "+f"(d[0]), "+f"(d[1]), "+f"(d[2]), "+f"(d[3])
        : "r"(a[0]), "r"(a[1]), "r"(a[2]), "r"(a[3]), "r"(b0), "r"(b1));
}
__device__ __forceinline__ void cp16(uint32_t dst, const void* src) {
    asm volatile("cp.async.cg.shared.global [%0], [%1], 16;" :: "r"(dst), "l"(src));
}
#define CP_COMMIT() asm volatile("cp.async.commit_group;" ::: "memory")
__device__ __forceinline__ void split2h(float v, __half& h, __half& l) {
    h = __float2half(v);
    l = __float2half(v - __half2float(h));
}

// stage layout: 3 tiles x 8KB = 24KB; 3 stages = 72KB
#define STG (24576)
#define GEMM_SMEM (3*STG)
#define BA_SMEM   (131072)

// non-trans tile [128 rows][32 k], 64B rows, swizzle c^((row>>1)&3)
#define OFF_NT(row, c) ((uint32_t)((row)<<6) + (uint32_t)(((c) ^ (((row)>>1)&3)) << 4))
// trans tile [32 k][128 n], 256B rows, swizzle c^(k&7)
#define OFF_T(k, c16)  ((uint32_t)((k)<<8) + (uint32_t)(((c16) ^ ((k)&7)) << 4))

// smem FFT pad
#define SWF(i) ((i) + ((((i)>>5))<<2))

// ============================================================
// GEMM core, both operands k-major:
// D(fp16) = A[128][256](single) @ (Bhi+Blo)[128][256]^T
// ============================================================
__device__ __forceinline__ void gemm_nn(
    const __half* __restrict__ A,
    const __half* __restrict__ Bhi, const __half* __restrict__ Blo,
    __half* __restrict__ D, int ldD, uint32_t sm)
{
    int tid = threadIdx.x;
    int wid = tid >> 5, lane = tid & 31;
    int wm = wid >> 1, wn = wid & 1;

    float acc[2][8][4];
    #pragma unroll
    for (int i=0;i<2;i++) for (int j=0;j<8;j++) for (int q=0;q<4;q++) acc[i][j][q] = 0.f;

    auto load_chunk = [&](int kc) {
        uint32_t base = sm + (kc % 3)*STG;
        #pragma unroll
        for (int e = tid; e < 512; e += 256) {
            int row = e >> 2, c = e & 3;
            uint32_t off = OFF_NT(row, c);
            size_t g = (size_t)row*256 + kc*32 + c*8;
            cp16(base          + off, A   + g);
            cp16(base +  8192  + off, Bhi + g);
            cp16(base + 16384  + off, Blo + g);
        }
        CP_COMMIT();
    };

    load_chunk(0); load_chunk(1); load_chunk(2);

    #pragma unroll 1
    for (int kc = 0; kc < 8; kc++) {
        if (kc < 6)      asm volatile("cp.async.wait_group 2;" ::: "memory");
        else if (kc == 6) asm volatile("cp.async.wait_group 1;" ::: "memory");
        else             asm volatile("cp.async.wait_group 0;" ::: "memory");
        __syncthreads();

        uint32_t base = sm + (kc % 3)*STG;
        uint32_t sA = base, sBhi = base + 8192, sBlo = base + 16384;

        #pragma unroll
        for (int ks = 0; ks < 2; ks++) {
            int c = ks*2 + (lane >> 4);
            uint32_t a[2][4];
            #pragma unroll
            for (int mi = 0; mi < 2; mi++) {
                int row = wm*32 + mi*16 + (lane & 15);
                uint32_t off = OFF_NT(row, c);
                ldsm_x4(a[mi][0], a[mi][1], a[mi][2], a[mi][3], sA + off);
            }
            uint32_t b[4][4];
            #pragma unroll
            for (int nj = 0; nj < 4; nj++) {
                int row = wn*64 + nj*16 + (lane & 7) + ((lane >> 3) & 1)*8;
                uint32_t off = OFF_NT(row, c);
                ldsm_x4(b[nj][0], b[nj][1], b[nj][2], b[nj][3], sBhi + off);
            }
            #pragma unroll
            for (int mi = 0; mi < 2; mi++)
                #pragma unroll
                for (int nj = 0; nj < 4; nj++) {
                    mma16816(acc[mi][nj*2],   a[mi], b[nj][0], b[nj][2]);
                    mma16816(acc[mi][nj*2+1], a[mi], b[nj][1], b[nj][3]);
                }
            #pragma unroll
            for (int nj = 0; nj < 4; nj++) {
                int row = wn*64 + nj*16 + (lane & 7) + ((lane >> 3) & 1)*8;
                uint32_t off = OFF_NT(row, c);
                ldsm_x4(b[nj][0], b[nj][1], b[nj][2], b[nj][3], sBlo + off);
            }
            #pragma unroll
            for (int mi = 0; mi < 2; mi++)
                #pragma unroll
                for (int nj = 0; nj < 4; nj++) {
                    mma16816(acc[mi][nj*2],   a[mi], b[nj][0], b[nj][2]);
                    mma16816(acc[mi][nj*2+1], a[mi], b[nj][1], b[nj][3]);
                }
        }
        __syncthreads();
        if (kc + 3 < 8) load_chunk(kc + 3);
    }

    int g = lane >> 2, tg = lane & 3;
    #pragma unroll
    for (int mi = 0; mi < 2; mi++) {
        int r0 = wm*32 + mi*16 + g;
        #pragma unroll
        for (int nt = 0; nt < 8; nt++) {
            int col = wn*64 + nt*8 + tg*2;
            __half2 v0, v1;
            v0.x = __float2half(acc[mi][nt][0]); v0.y = __float2half(acc[mi][nt][1]);
            v1.x = __float2half(acc[mi][nt][2]); v1.y = __float2half(acc[mi][nt][3]);
            *(__half2*)&D[(size_t)r0*ldD + col]     = v0;
            *(__half2*)&D[(size_t)(r0+8)*ldD + col] = v1;
        }
    }
}

// ============================================================
// GEMM core, A k-major (hi+lo), B row-major [256 k][N] (single, trans).
// Fused GroupNorm partial stats (from fp32 accumulators). D stored fp16.
// ============================================================
__device__ __forceinline__ void gemm_kn(
    const __half* __restrict__ Ahi, const __half* __restrict__ Alo,
    const __half* __restrict__ Bh, size_t ldB,
    __half* __restrict__ D, int ldD, const float* __restrict__ bias, uint32_t sm,
    char* smc, float* cps, float* cps2, int blin)
{
    int tid = threadIdx.x;
    int wid = tid >> 5, lane = tid & 31;
    int wm = wid >> 1, wn = wid & 1;

    float acc[2][8][4];
    #pragma unroll
    for (int i=0;i<2;i++) for (int j=0;j<8;j++) for (int q=0;q<4;q++) acc[i][j][q] = 0.f;

    auto load_chunk = [&](int kc) {
        uint32_t base = sm + (kc % 3)*STG;
        #pragma unroll
        for (int e = tid; e < 512; e += 256) {
            int row = e >> 2, c = e & 3;
            uint32_t off = OFF_NT(row, c);
            size_t gA = (size_t)row*256 + kc*32 + c*8;
            cp16(base         + off, Ahi + gA);
            cp16(base +  8192 + off, Alo + gA);
            int kr = e >> 4, c16 = e & 15;
            uint32_t offb = OFF_T(kr, c16);
            size_t gB = (size_t)(kc*32 + kr)*ldB + c16*8;
            cp16(base + 16384 + offb, Bh + gB);
        }
        CP_COMMIT();
    };

    load_chunk(0); load_chunk(1); load_chunk(2);

    #pragma unroll 1
    for (int kc = 0; kc < 8; kc++) {
        if (kc < 6)      asm volatile("cp.async.wait_group 2;" ::: "memory");
        else if (kc == 6) asm volatile("cp.async.wait_group 1;" ::: "memory");
        else             asm volatile("cp.async.wait_group 0;" ::: "memory");
        __syncthreads();

        uint32_t base = sm + (kc % 3)*STG;
        uint32_t sAhi = base, sAlo = base + 8192, sBh = base + 16384;

        #pragma unroll
        for (int ks = 0; ks < 2; ks++) {
            int c = ks*2 + (lane >> 4);
            uint32_t a_h[2][4], a_l[2][4];
            #pragma unroll
            for (int mi = 0; mi < 2; mi++) {
                int row = wm*32 + mi*16 + (lane & 15);
                uint32_t off = OFF_NT(row, c);
                ldsm_x4(a_h[mi][0], a_h[mi][1], a_h[mi][2], a_h[mi][3], sAhi + off);
                ldsm_x4(a_l[mi][0], a_l[mi][1], a_l[mi][2], a_l[mi][3], sAlo + off);
            }
            int kr = ks*16 + (lane & 7) + ((lane >> 3) & 1)*8;
            uint32_t b[4][4];
            #pragma unroll
            for (int nj = 0; nj < 4; nj++) {
                int n = wn*64 + nj*16 + ((lane >> 4) & 1)*8;
                uint32_t off = OFF_T(kr, (n >> 3));
                ldsm_x4_t(b[nj][0], b[nj][1], b[nj][2], b[nj][3], sBh + off);
            }
            #pragma unroll
            for (int mi = 0; mi < 2; mi++)
                #pragma unroll
                for (int nj = 0; nj < 4; nj++) {
                    mma16816(acc[mi][nj*2],   a_h[mi], b[nj][0], b[nj][1]);
                    mma16816(acc[mi][nj*2+1], a_h[mi], b[nj][2], b[nj][3]);
                }
            #pragma unroll
            for (int mi = 0; mi < 2; mi++)
                #pragma unroll
                for (int nj = 0; nj < 4; nj++) {
                    mma16816(acc[mi][nj*2],   a_l[mi], b[nj][0], b[nj][1]);
                    mma16816(acc[mi][nj*2+1], a_l[mi], b[nj][2], b[nj][3]);
                }
        }
        __syncthreads();
        if (kc + 3 < 8) load_chunk(kc + 3);
    }

    int g = lane >> 2, tg = lane & 3;
    int slot = wn*4 + tg;
    float* srow  = (float*)smc;          // [128][8]
    float* srow2 = srow + 1024;          // [128][8]
    float* rtot  = srow + 2048;          // [128]
    float* rtot2 = srow + 2176;          // [128]
    #pragma unroll
    for (int mi = 0; mi < 2; mi++) {
        int r0 = wm*32 + mi*16 + g;
        float bv0 = bias[r0], bv1 = bias[r0+8];
        float s0=0.f, q0=0.f, s1=0.f, q1=0.f;
        #pragma unroll
        for (int nt = 0; nt < 8; nt++) {
            int col = wn*64 + nt*8 + tg*2;
            float v0 = acc[mi][nt][0] + bv0, v1 = acc[mi][nt][1] + bv0;
            float v2 = acc[mi][nt][2] + bv1, v3 = acc[mi][nt][3] + bv1;
            __half2 p0, p1;
            p0.x = __float2half(v0); p0.y = __float2half(v1);
            p1.x = __float2half(v2); p1.y = __float2half(v3);
            *(__half2*)&D[(size_t)r0*ldD + col]     = p0;
            *(__half2*)&D[(size_t)(r0+8)*ldD + col] = p1;
            s0 += v0 + v1; q0 += v0*v0 + v1*v1;
            s1 += v2 + v3; q1 += v2*v2 + v3*v3;
        }
        srow [r0*8 + slot] = s0;  srow2[r0*8 + slot] = q0;
        srow [(r0+8)*8 + slot] = s1;  srow2[(r0+8)*8 + slot] = q1;
    }
    __syncthreads();
    if (tid < 128) {
        float s=0.f, q=0.f;
        #pragma unroll
        for (int j = 0; j < 8; j++) { s += srow[tid*8+j]; q += srow2[tid*8+j]; }
        rtot[tid] = s; rtot2[tid] = q;
    }
    __syncthreads();
    if (tid < 16) {
        float s=0.f, q=0.f;
        #pragma unroll
        for (int j = 0; j < 8; j++) { s += rtot[tid*8+j]; q += rtot2[tid*8+j]; }
        cps [blin*16 + tid] = s;
        cps2[blin*16 + tid] = q;
    }
}

// ============================================================
// Stage 0: split conv weights + fill twiddle tables (block 0).
// ============================================================
__global__ void k_wsplit(const float* __restrict__ w) {
    int i = blockIdx.x*256 + threadIdx.x;   // 65536 total
    __half h, l;
    split2h(w[i], h, l);
    d_Whi[i] = h; d_Wlo[i] = l;
    if (blockIdx.x == 0) {
        int t = threadIdx.x;
        if (t < 256) { float s,c; sincosf(6.283185307179586f*(float)t/256.0f,&s,&c); g_tw256[t]=make_float2(c,-s); }
        if (t < 129) { float s,c; sincosf(-6.283185307179586f*(float)t/512.0f,&s,&c); g_u512[t]=make_float2(c,s); }
        if (t < 128) { float s,c; sincosf(6.283185307179586f*(float)t/128.0f,&s,&c); g_tw128[t]=make_float2(c,s); }
        if (t < 128) { float s,c; sincosf(6.283185307179586f*(float)t/256.0f,&s,&c); g_w256[t]=make_float2(c,s); }
    }
}

// ============================================================
// Stage 1: rfft(512) per row via packed radix-4 256-pt FFT. Output single fp16.
// ============================================================
__global__ void __launch_bounds__(512) k_fft_fwd(const float* __restrict__ x) {
    __shared__ float sre[16*288];
    __shared__ float sim[16*288];
    __shared__ float2 tw[256];
    __shared__ float2 ue[129];
    int tid = threadIdx.x;
    if (tid < 256) tw[tid] = g_tw256[tid];
    if (tid < 129) ue[tid] = g_u512[tid];
    __syncthreads();
    int w = tid >> 5, lane = tid & 31;
    float* re = sre + w*288;
    float* im = sim + w*288;
    int row = blockIdx.x*16 + w;
    const float4* xr4 = (const float4*)(x + (size_t)row*512);
    #pragma unroll
    for (int j = 0; j < 4; j++) {
        float4 v = xr4[lane + 32*j];
        int f  = lane + 32*j;
        int r0 = __brev(2*f)   >> 24;
        int r1 = __brev(2*f+1) >> 24;
        re[SWF(r0)]=v.x; im[SWF(r0)]=v.y;
        re[SWF(r1)]=v.z; im[SWF(r1)]=v.w;
    }
    __syncwarp();
    #pragma unroll
    for (int h = 0; h < 2; h++) {
        int p = 4*(lane + 32*h);
        int a = SWF(p);
        float4 vr = *(float4*)&re[a];
        float4 vi = *(float4*)&im[a];
        float t0r=vr.x,t0i=vi.x, t1r=vr.z,t1i=vi.z, t2r=vr.y,t2i=vi.y, t3r=vr.w,t3i=vi.w;
        float s0r=t0r+t2r, s0i=t0i+t2i, d0r=t0r-t2r, d0i=t0i-t2i;
        float s1r=t1r+t3r, s1i=t1i+t3i, d1r=t1r-t3r, d1i=t1i-t3i;
        float4 yr, yi;
        yr.x = s0r+s1r; yi.x = s0i+s1i;
        yr.y = d0r+d1i; yi.y = d0i-d1r;
        yr.z = s0r-s1r; yi.z = s0i-s1i;
        yr.w = d0r-d1i; yi.w = d0i+d1r;
        *(float4*)&re[a] = yr; *(float4*)&im[a] = yi;
    }
    __syncwarp();
    #pragma unroll
    for (int rq = 0; rq < 3; rq++) {
        int Q = 4 << (2*rq);
        int step = 16 >> (2*rq);
        #pragma unroll
        for (int h = 0; h < 2; h++) {
            int b = lane + 32*h;
            int j = b & (Q-1);
            int p = ((b & ~(Q-1)) << 2) + j;
            float2 w1 = tw[(j*step) & 255];
            float2 w2 = tw[(2*j*step) & 255];
            float2 w3 = tw[(3*j*step) & 255];
            int a0 = SWF(p), a1 = SWF(p+2*Q), a2 = SWF(p+Q), a3 = SWF(p+3*Q);
            float x0r=re[a0], x0i=im[a0];
            float x1r=re[a1], x1i=im[a1];
            float x2r=re[a2], x2i=im[a2];
            float x3r=re[a3], x3i=im[a3];
            float t1r = x1r*w1.x - x1i*w1.y, t1i = x1r*w1.y + x1i*w1.x;
            float t2r = x2r*w2.x - x2i*w2.y, t2i = x2r*w2.y + x2i*w2.x;
            float t3r = x3r*w3.x - x3i*w3.y, t3i = x3r*w3.y + x3i*w3.x;
            float s0r=x0r+t2r, s0i=x0i+t2i, d0r=x0r-t2r, d0i=x0i-t2i;
            float s1r=t1r+t3r, s1i=t1i+t3i, d1r=t1r-t3r, d1i=t1i-t3i;
            re[a0]=s0r+s1r; im[a0]=s0i+s1i;
            re[a2]=d0r+d1i; im[a2]=d0i-d1r;
            re[a1]=s0r-s1r; im[a1]=s0i-s1i;
            re[a3]=d0r-d1i; im[a3]=d0i+d1r;
        }
        __syncwarp();
    }
    const float SC = 0.012271846303085129f;  // 2*pi/512
    float ro[5], io[5];
    #pragma unroll
    for (int j = 0; j < 5; j++) {
        int k = lane + 32*j;
        if (k <= 128) {
            int km = (256-k) & 255;
            float zr=re[SWF(k)],  zi= im[SWF(k)];
            float mr=re[SWF(km)], mi=-im[SWF(km)];
            float er=0.5f*(zr+mr), ei=0.5f*(zi+mi);
            float dr=0.5f*(zr-mr), di=0.5f*(zi-mi);
            float pr=di, pi=-dr;
            float wr=ue[k].x, wi=ue[k].y;
            float qr=pr*wr-pi*wi, qi=pr*wi+pi*wr;
            ro[j] = (er+qr)*SC;
            io[j] = (ei+qi)*SC;
        }
    }
    __syncthreads();
    float* ore = sre;   // reuse: [129][16]
    float* oim = sim;
    #pragma unroll
    for (int j = 0; j < 5; j++) {
        int k = lane + 32*j;
        if (k <= 128) { ore[k*16+w] = ro[j]; oim[k*16+w] = io[j]; }
    }
    __syncthreads();
    int base = blockIdx.x*16;
    for (int idx = tid; idx < 129*8; idx += 512) {
        int m = idx >> 3, rr = (idx & 7) << 1;
        size_t o = (size_t)m*ROWS1 + base + rr;
        __half2 v;
        v.x = __float2half(ore[m*16+rr]);
        v.y = __float2half(ore[m*16+rr+1]);
        *(__half2*)&d_Xr[o] = v;
        v.x = __float2half(oim[m*16+rr]);
        v.y = __float2half(oim[m*16+rr+1]);
        *(__half2*)&d_Xi[o] = v;
    }
}

// ============================================================
// Stage 2c: At[m][klo][kh] = sum_l P[l][klo] W[l][kh] via fp16 3-term mma.
// ============================================================
__global__ void __launch_bounds__(256) k_buildA_mma(const float* __restrict__ wmat,
                                                    const float* __restrict__ pct) {
    extern __shared__ __align__(128) char dsm[];
    uint32_t sm = smem_u32(dsm);
    int tid = threadIdx.x;
    int wid = tid >> 5, lane = tid & 31;
    int wm = wid >> 1, wn = wid & 1;
    int m = blockIdx.y, kh0 = blockIdx.x * 128;

    const float* Pg = pct  + (size_t)m*LMAX*HLO;
    const float* Wg = wmat + (size_t)m*LMAX*HHI + kh0;

    #pragma unroll
    for (int p = 0; p < 8; p++) {
        int gi = p*256 + tid;
        int l = gi >> 4, c16 = gi & 15;
        uint32_t off = (uint32_t)((l >> 5) << 13) + OFF_T(l & 31, c16);
        {
            const float* sp = Pg + (size_t)l*HLO + c16*8;
            float4 v0 = *(const float4*)sp;
            float4 v1 = *(const float4*)(sp+4);
            __half h[8], lo[8];
            split2h(v0.x,h[0],lo[0]); split2h(v0.y,h[1],lo[1]); split2h(v0.z,h[2],lo[2]); split2h(v0.w,h[3],lo[3]);
            split2h(v1.x,h[4],lo[4]); split2h(v1.y,h[5],lo[5]); split2h(v1.z,h[6],lo[6]); split2h(v1.w,h[7],lo[7]);
            *(uint4*)(dsm + off)          = *(uint4*)h;
            *(uint4*)(dsm + 32768 + off)  = *(uint4*)lo;
        }
        {
            const float* sw = Wg + (size_t)l*HHI + c16*8;
            float4 v0 = *(const float4*)sw;
            float4 v1 = *(const float4*)(sw+4);
            __half h[8], lo[8];
            split2h(v0.x,h[0],lo[0]); split2h(v0.y,h[1],lo[1]); split2h(v0.z,h[2],lo[2]); split2h(v0.w,h[3],lo[3]);
            split2h(v1.x,h[4],lo[4]); split2h(v1.y,h[5],lo[5]); split2h(v1.z,h[6],lo[6]); split2h(v1.w,h[7],lo[7]);
            *(uint4*)(dsm + 65536 + off)  = *(uint4*)h;
            *(uint4*)(dsm + 98304 + off)  = *(uint4*)lo;
        }
    }
    __syncthreads();

    float acc[2][8][4];
    #pragma unroll
    for (int i=0;i<2;i++) for (int j=0;j<8;j++) for (int q=0;q<4;q++) acc[i][j][q] = 0.f;

    #pragma unroll 1
    for (int kc = 0; kc < 4; kc++) {
        uint32_t cb = (uint32_t)(kc << 13);
        uint32_t sPh = sm + cb, sPl = sm + 32768 + cb, sWh = sm + 65536 + cb, sWl = sm + 98304 + cb;

        #pragma unroll
        for (int ks = 0; ks < 2; ks++) {
            int kr = ks*16 + (lane & 7) + ((lane >> 3) & 1)*8;
            uint32_t a_h[2][4], a_l[2][4];
            #pragma unroll
            for (int mi = 0; mi < 2; mi++) {
                int mcol = wm*4 + mi*2 + ((lane >> 4) & 1);
                uint32_t off = OFF_T(kr, mcol);
                uint32_t r0,r1,r2,r3;
                ldsm_x4_t(r0, r1, r2, r3, sPh + off);
                a_h[mi][0]=r0; a_h[mi][1]=r2; a_h[mi][2]=r1; a_h[mi][3]=r3;
                ldsm_x4_t(r0, r1, r2, r3, sPl + off);
                a_l[mi][0]=r0; a_l[mi][1]=r2; a_l[mi][2]=r1; a_l[mi][3]=r3;
            }
            uint32_t b[4][4];
            #pragma unroll
            for (int nj = 0; nj < 4; nj++) {
                int n = wn*64 + nj*16 + ((lane >> 4) & 1)*8;
                uint32_t off = OFF_T(kr, (n >> 3));
                ldsm_x4_t(b[nj][0], b[nj][1], b[nj][2], b[nj][3], sWh + off);
            }
            #pragma unroll
            for (int mi = 0; mi < 2; mi++)
                #pragma unroll
                for (int nj = 0; nj < 4; nj++) {
                    mma16816(acc[mi][nj*2],   a_h[mi], b[nj][0], b[nj][1]);
                    mma16816(acc[mi][nj*2+1], a_h[mi], b[nj][2], b[nj][3]);
                }
            #pragma unroll
            for (int mi = 0; mi < 2; mi++)
                #pragma unroll
                for (int nj = 0; nj < 4; nj++) {
                    mma16816(acc[mi][nj*2],   a_l[mi], b[nj][0], b[nj][1]);
                    mma16816(acc[mi][nj*2+1], a_l[mi], b[nj][2], b[nj][3]);
                }
            #pragma unroll
            for (int nj = 0; nj < 4; nj++) {
                int n = wn*64 + nj*16 + ((lane >> 4) & 1)*8;
                uint32_t off = OFF_T(kr, (n >> 3));
                ldsm_x4_t(b[nj][0], b[nj][1], b[nj][2], b[nj][3], sWl + off);
            }
            #pragma unroll
            for (int mi = 0; mi < 2; mi++)
                #pragma unroll
                for (int nj = 0; nj < 4; nj++) {
                    mma16816(acc[mi][nj*2],   a_h[mi], b[nj][0], b[nj][1]);
                    mma16816(acc[mi][nj*2+1], a_h[mi], b[nj][2], b[nj][3]);
                }
        }
    }

    int g = lane >> 2, tg = lane & 3;
    size_t Abase = (size_t)m*(HLO*HHI);
    #pragma unroll
    for (int mi = 0; mi < 2; mi++) {
        #pragma unroll
        for (int half = 0; half < 2; half++) {
            int r = wm*32 + mi*16 + g + half*8;
            #pragma unroll
            for (int nt = 0; nt < 8; nt++) {
                int col = kh0 + wn*64 + nt*8 + tg*2;
                __half h0,l0,h1,l1;
                split2h(acc[mi][nt][half*2],   h0, l0);
                split2h(acc[mi][nt][half*2+1], h1, l1);
                __half2 vh; vh.x=h0; vh.y=h1;
                __half2 vl; vl.x=l0; vl.y=l1;
                *(__half2*)&d_At_hi[Abase + (size_t)r*HHI + col] = vh;
                *(__half2*)&d_At_lo[Abase + (size_t)r*HHI + col] = vl;
            }
        }
    }
}

// ============================================================
// Stage 3: Legendre per-m GEMM (X single, At hi/lo). G fp16.
// ============================================================
__global__ void __launch_bounds__(256) k_legendre_mma() {
    extern __shared__ __align__(128) char dsm[];
    int m = blockIdx.y;
    int bx = blockIdx.x;
    int half = bx >> 2;
    int bc0  = (bx & 3) * 128;
    size_t xo = (size_t)m*ROWS1 + (size_t)bc0*HHI;
    const __half* A;
    __half* D;
    if (half) { A = d_Xi + xo; D = d_Gi; }
    else      { A = d_Xr + xo; D = d_Gr; }
    D += (size_t)m*ROWS2 + (size_t)bc0*HLO;
    const __half* Bh = d_At_hi + (size_t)m*(HLO*HHI);
    const __half* Bl = d_At_lo + (size_t)m*(HLO*HHI);
    gemm_nn(A, Bh, Bl, D, HLO, smem_u32(dsm));
}

// ============================================================
// Stage 4: irfft(n=256)*256 per row. G fp16 in, single fp16 out.
// ============================================================
__global__ void __launch_bounds__(512) k_ifft() {
    __shared__ float gre[129*16], gim[129*16];
    __shared__ float sre[16*144], sim[16*144];
    __shared__ float2 tw2[128];
    __shared__ float2 wq[128];
    int tid = threadIdx.x;
    if (tid < 128) tw2[tid] = g_tw128[tid];
    if (tid >= 128 && tid < 256) wq[tid-128] = g_w256[tid-128];
    int base = blockIdx.x*16;
    for (int idx = tid; idx < 129*16; idx += 512) {
        int m = idx >> 4, r = idx & 15;
        gre[idx] = __half2float(d_Gr[m*ROWS2 + base + r]);
        gim[idx] = __half2float(d_Gi[m*ROWS2 + base + r]);
    }
    __syncthreads();
    int w = tid >> 5, lane = tid & 31;
    float* re = sre + w*144;
    float* im = sim + w*144;
    #pragma unroll 4
    for (int k = lane; k < 128; k += 32) {
        float ar = gre[k*16+w],        ai =  gim[k*16+w];
        float br = gre[(128-k)*16+w],  bi = -gim[(128-k)*16+w];
        float wr = wq[k].x, wi = wq[k].y;
        float c1r = 1.f - wi, c1i =  wr;
        float c2r = 1.f + wi, c2i = -wr;
        float Zr = ar*c1r - ai*c1i + br*c2r - bi*c2i;
        float Zi = ar*c1i + ai*c1r + br*c2i + bi*c2r;
        int rv = __brev(k) >> 25;
        re[SWF(rv)] = Zr; im[SWF(rv)] = Zi;
    }
    __syncwarp();
    {
        int p = 4*lane;
        int a = SWF(p);
        float4 vr = *(float4*)&re[a];
        float4 vi = *(float4*)&im[a];
        float t0r=vr.x,t0i=vi.x, t1r=vr.z,t1i=vi.z, t2r=vr.y,t2i=vi.y, t3r=vr.w,t3i=vi.w;
        float s0r=t0r+t2r, s0i=t0i+t2i, d0r=t0r-t2r, d0i=t0i-t2i;
        float s1r=t1r+t3r, s1i=t1i+t3i, d1r=t1r-t3r, d1i=t1i-t3i;
        float4 yr, yi;
        yr.x = s0r+s1r; yi.x = s0i+s1i;
        yr.y = d0r-d1i; yi.y = d0i+d1r;
        yr.z = s0r-s1r; yi.z = s0i-s1i;
        yr.w = d0r+d1i; yi.w = d0i-d1r;
        *(float4*)&re[a] = yr; *(float4*)&im[a] = yi;
    }
    __syncwarp();
    #pragma unroll
    for (int rq = 0; rq < 2; rq++) {
        int Q = 4 << (2*rq);
        int step = 8 >> (2*rq);
        int b = lane;
        int j = b & (Q-1);
        int p = ((b & ~(Q-1)) << 2) + j;
        float2 w1 = tw2[(j*step) & 127];
        float2 w2 = tw2[(2*j*step) & 127];
        float2 w3 = tw2[(3*j*step) & 127];
        int a0 = SWF(p), a1 = SWF(p+2*Q), a2 = SWF(p+Q), a3 = SWF(p+3*Q);
        float x0r=re[a0], x0i=im[a0];
        float x1r=re[a1], x1i=im[a1];
        float x2r=re[a2], x2i=im[a2];
        float x3r=re[a3], x3i=im[a3];
        float t1r = x1r*w1.x - x1i*w1.y, t1i = x1r*w1.y + x1i*w1.x;
        float t2r = x2r*w2.x - x2i*w2.y, t2i = x2r*w2.y + x2i*w2.x;
        float t3r = x3r*w3.x - x3i*w3.y, t3i = x3r*w3.y + x3i*w3.x;
        float s0r=x0r+t2r, s0i=x0i+t2i, d0r=x0r-t2r, d0i=x0i-t2i;
        float s1r=t1r+t3r, s1i=t1i+t3i, d1r=t1r-t3r, d1i=t1i-t3i;
        re[a0]=s0r+s1r; im[a0]=s0i+s1i;
        re[a2]=d0r-d1i; im[a2]=d0i+d1r;
        re[a1]=s0r-s1r; im[a1]=s0i-s1i;
        re[a3]=d0r+d1i; im[a3]=d0i-d1r;
        __syncwarp();
    }
    #pragma unroll
    for (int h = 0; h < 2; h++) {
        int p = lane + 32*h;
        float2 wv = tw2[p];
        int a0 = SWF(p), a1 = SWF(p+64);
        float x0r=re[a0], x0i=im[a0];
        float x1r=re[a1], x1i=im[a1];
        float tr = x1r*wv.x - x1i*wv.y, ti = x1r*wv.y + x1i*wv.x;
        re[a0]=x0r+tr; im[a0]=x0i+ti;
        re[a1]=x0r-tr; im[a1]=x0i-ti;
    }
    __syncwarp();
    __half2* yh = (__half2*)d_Yc + (size_t)(base + w)*128;
    #pragma unroll 4
    for (int n = lane; n < 128; n += 32) {
        __half2 v;
        v.x = __float2half(re[SWF(n)]);
        v.y = __float2half(im[SWF(n)]);
        yh[n] = v;
    }
}

// ============================================================
// Stage 5: 1x1 conv + fused GN partial stats. H stored fp16.
// ============================================================
__global__ void __launch_bounds__(256) k_conv_mma(const float* __restrict__ bias) {
    extern __shared__ __align__(128) char dsm[];
    int b = blockIdx.z, o0 = blockIdx.y*128, hw0 = blockIdx.x*128;
    int blin = (b*2 + blockIdx.y)*256 + blockIdx.x;
    const __half* Ah = d_Whi + (size_t)o0*CIN;
    const __half* Al = d_Wlo + (size_t)o0*CIN;
    const __half* Bh = d_Yc + (size_t)b*CIN*HWLO + hw0;
    __half* D = d_Hh + ((size_t)b*COUT + o0)*HWLO + hw0;
    gemm_kn(Ah, Al, Bh, (size_t)HWLO, D, HWLO, bias + o0, smem_u32(dsm),
            dsm, d_cps, d_cps2, blin);
}

// ============================================================
// Stage 6: GroupNorm final stats — 64 blocks, parallel tree.
// ============================================================
__global__ void k_gnfin() {
    __shared__ double sh[256], sh2[256];
    int bg = blockIdx.x;
    int b = bg >> 5, g = bg & 31;
    int y = g >> 4, gi = g & 15;
    int t = threadIdx.x;
    int idx = ((b*2 + y)*256 + t)*16 + gi;
    sh[t]  = (double)d_cps [idx];
    sh2[t] = (double)d_cps2[idx];
    __syncthreads();
    for (int st = 128; st > 0; st >>= 1) {
        if (t < st) { sh[t] += sh[t+st]; sh2[t] += sh2[t+st]; }
        __syncthreads();
    }
    if (t == 0) {
        const double N = (double)(CPG*HWLO);
        double mean = sh[0] / N;
        double var  = sh2[0] / N - mean*mean;
        d_mean[bg] = (float)mean;
        d_rstd[bg] = rsqrtf((float)var + 1e-5f);
    }
}

// ============================================================
// Stage 7: normalize + affine + exact GELU (8 halves/thread)
// ============================================================
__global__ void k_gnapply(const float* __restrict__ gamma, const float* __restrict__ beta,
                          float* __restrict__ out) {
    int base = blockIdx.x*256 + threadIdx.x;   // uint4 index: 8 halves
    uint4 hv = ((const uint4*)d_Hh)[base];
    int e0 = base * 8;
    int o  = (e0 >> 15) & 255;
    int bg = e0 >> 18;
    float a  = gamma[o] * d_rstd[bg];
    float b2 = beta[o] - d_mean[bg] * a;
    __half2* hp = (__half2*)&hv;
    float4 r0, r1;
    float v[8];
    #pragma unroll
    for (int j = 0; j < 4; j++) {
        float2 f = __half22float2(hp[j]);
        v[2*j]   = f.x*a + b2;
        v[2*j+1] = f.y*a + b2;
    }
    r0.x = v[0]*normcdff(v[0]); r0.y = v[1]*normcdff(v[1]);
    r0.z = v[2]*normcdff(v[2]); r0.w = v[3]*normcdff(v[3]);
    r1.x = v[4]*normcdff(v[4]); r1.y = v[5]*normcdff(v[5]);
    r1.z = v[6]*normcdff(v[6]); r1.w = v[7]*normcdff(v[7]);
    ((float4*)out)[base*2]     = r0;
    ((float4*)out)[base*2 + 1] = r1;
}

// ============================================================
extern "C" void kernel_launch(void* const* d_in, const int* in_sizes, int n_in,
                              void* d_out, int out_size) {
    const float* x      = (const float*)d_in[0];
    const float* conv_w = (const float*)d_in[1];
    const float* conv_b = (const float*)d_in[2];
    const float* gamma  = (const float*)d_in[3];
    const float* beta   = (const float*)d_in[4];
    const float* wmat   = (const float*)d_in[5];
    const float* pct    = (const float*)d_in[6];
    float* out = (float*)d_out;

    cudaFuncSetAttribute(k_buildA_mma,   cudaFuncAttributeMaxDynamicSharedMemorySize, BA_SMEM);
    cudaFuncSetAttribute(k_legendre_mma, cudaFuncAttributeMaxDynamicSharedMemorySize, GEMM_SMEM);
    cudaFuncSetAttribute(k_conv_mma,     cudaFuncAttributeMaxDynamicSharedMemorySize, GEMM_SMEM);

    k_wsplit      <<<256, 256>>>(conv_w);
    k_fft_fwd     <<<ROWS1/16, 512>>>(x);
    k_buildA_mma  <<<dim3(2, MMAX), 256, BA_SMEM>>>(wmat, pct);
    k_legendre_mma<<<dim3(8, MMAX), 256, GEMM_SMEM>>>();
    k_ifft        <<<ROWS2/16, 512>>>();
    k_conv_mma    <<<dim3(HWLO/128, COUT/128, BATCH), 256, GEMM_SMEM>>>(conv_b);
    k_gnfin       <<<64, 256>>>();
    k_gnapply     <<<(BC*HWLO)/8/256, 256>>>(gamma, beta, out);
}